// round 14
// baseline (speedup 1.0000x reference)
#include <cuda_runtime.h>
#include <cuda_fp16.h>
#include <stdint.h>
#include <math.h>

#define BB 4
#define CC 128
#define HWH 16384
#define NPIX 65536
#define INNER 512
#define NP 1536
#define MAXNEG -3.402823466e38f

// fp16 scratch (10-bit mantissa == tf32 mantissa; like-for-like rounding)
__device__ __half g_Ph[(size_t)NPIX * NP];     // [q(512, pre-scaled) | k(512) | v(512)]
__device__ __half g_AOh[(size_t)NPIX * INNER];

__device__ __forceinline__ void mma16h(float* c,
                                       uint32_t a0, uint32_t a1, uint32_t a2, uint32_t a3,
                                       uint32_t b0, uint32_t b1) {
    asm volatile("mma.sync.aligned.m16n8k16.row.col.f32.f16.f16.f32 "
        "{%0,%1,%2,%3}, {%4,%5,%6,%7}, {%8,%9}, {%0,%1,%2,%3};"
        : "+f"(c[0]), "+f"(c[1]), "+f"(c[2]), "+f"(c[3])
        : "r"(a0), "r"(a1), "r"(a2), "r"(a3), "r"(b0), "r"(b1));
}
__device__ __forceinline__ uint32_t packh2(float lo, float hi) {
    __half2 h = __floats2half2_rn(lo, hi);
    return *(uint32_t*)&h;
}
__device__ __forceinline__ void ldsm4(uint32_t* r, uint32_t addr) {
    asm volatile("ldmatrix.sync.aligned.m8n8.x4.shared.b16 {%0,%1,%2,%3}, [%4];"
        : "=r"(r[0]), "=r"(r[1]), "=r"(r[2]), "=r"(r[3]) : "r"(addr));
}
__device__ __forceinline__ void ldsm4t(uint32_t* r, uint32_t addr) {
    asm volatile("ldmatrix.sync.aligned.m8n8.x4.trans.shared.b16 {%0,%1,%2,%3}, [%4];"
        : "=r"(r[0]), "=r"(r[1]), "=r"(r[2]), "=r"(r[3]) : "r"(addr));
}

// ---------------------------------------------------------------------------
// Kernel 1: P[p,:] = x_pixel[p,:] @ [Wq*0.125 | Wkv].  f16 MMA + ldmatrix.
// (exact R11 version — proven 218us, 2 CTAs/SM)
// ---------------------------------------------------------------------------
#define SH1 136
__global__ void __launch_bounds__(256) k_proj(const float* __restrict__ x,
                                              const float* __restrict__ Wq,
                                              const float* __restrict__ Wkv) {
    extern __shared__ __half smh[];
    __half* Ah = smh;              // [64][136]
    __half* Bh = smh + 64 * SH1;   // [64][136]

    const int t = threadIdx.x, w = t >> 5, lane = t & 31;
    const int qsel = lane >> 3, rsel = lane & 7;
    const int g = lane >> 2, tq = lane & 3;
    const int m0w = (w & 1) * 64, n0w = (w >> 1) * 32;
    const int jt = blockIdx.x;                 // 0..3 Wq, 4..11 Wkv
    const int p0 = blockIdx.y * 128;
    const int b  = p0 >> 14;
    const int y  = (p0 & (HWH - 1)) >> 7;

    float acc[4][4][4];
    #pragma unroll
    for (int mt = 0; mt < 4; mt++)
        #pragma unroll
        for (int nt = 0; nt < 4; nt++)
            #pragma unroll
            for (int e = 0; e < 4; e++) acc[mt][nt][e] = 0.f;

    const uint32_t aB = (uint32_t)__cvta_generic_to_shared(Ah);
    const uint32_t bB = (uint32_t)__cvta_generic_to_shared(Bh);

    for (int kc = 0; kc < 2; kc++) {
        const int K0 = kc * 64;
        __syncthreads();
        const float* xb = x + ((size_t)(b * CC + K0) * 128 + y) * 128;
        for (int idx = t; idx < 64 * 32; idx += 256) {
            int k = idx >> 5, m4 = (idx & 31) * 4;
            float4 v = *(const float4*)(xb + (size_t)k * HWH + m4);
            uint2 hv;
            hv.x = packh2(v.x, v.y);
            hv.y = packh2(v.z, v.w);
            *(uint2*)&Ah[k * SH1 + m4] = hv;
        }
        if (jt < 4) {
            const float* Wb = Wq + (size_t)K0 * INNER + jt * 128;
            for (int idx = t; idx < 64 * 32; idx += 256) {
                int k = idx >> 5, n4 = (idx & 31) * 4;
                float4 v = *(const float4*)(Wb + (size_t)k * INNER + n4);
                uint2 hv;
                hv.x = packh2(v.x * 0.125f, v.y * 0.125f);
                hv.y = packh2(v.z * 0.125f, v.w * 0.125f);
                *(uint2*)&Bh[k * SH1 + n4] = hv;
            }
        } else {
            const float* Wb = Wkv + (size_t)K0 * 1024 + (jt - 4) * 128;
            for (int idx = t; idx < 64 * 32; idx += 256) {
                int k = idx >> 5, n4 = (idx & 31) * 4;
                float4 v = *(const float4*)(Wb + (size_t)k * 1024 + n4);
                uint2 hv;
                hv.x = packh2(v.x, v.y);
                hv.y = packh2(v.z, v.w);
                *(uint2*)&Bh[k * SH1 + n4] = hv;
            }
        }
        __syncthreads();

        #pragma unroll
        for (int ks16 = 0; ks16 < 4; ks16++) {
            const int k0 = ks16 * 16;
            const int kkA = k0 + (qsel >> 1) * 8 + rsel;
            uint32_t af[4][4];
            #pragma unroll
            for (int mt = 0; mt < 4; mt++) {
                int m = m0w + mt * 16 + (qsel & 1) * 8;
                ldsm4t(af[mt], aB + (uint32_t)((kkA * SH1 + m) * 2));
            }
            const int kkB = k0 + (qsel & 1) * 8 + rsel;
            uint32_t bf[4][2];
            #pragma unroll
            for (int h = 0; h < 2; h++) {
                int n = n0w + h * 16 + (qsel >> 1) * 8;
                uint32_t r4[4];
                ldsm4t(r4, bB + (uint32_t)((kkB * SH1 + n) * 2));
                bf[2 * h][0] = r4[0]; bf[2 * h][1] = r4[1];
                bf[2 * h + 1][0] = r4[2]; bf[2 * h + 1][1] = r4[3];
            }
            #pragma unroll
            for (int nt = 0; nt < 4; nt++)
                #pragma unroll
                for (int mt = 0; mt < 4; mt++)
                    mma16h(acc[mt][nt], af[mt][0], af[mt][1], af[mt][2], af[mt][3],
                           bf[nt][0], bf[nt][1]);
        }
    }

    const int colb = jt * 128;
    #pragma unroll
    for (int mt = 0; mt < 4; mt++) {
        int m = m0w + mt * 16 + g;
        #pragma unroll
        for (int nt = 0; nt < 4; nt++) {
            int n = colb + n0w + nt * 8 + tq * 2;
            *(__half2*)&g_Ph[(size_t)(p0 + m) * NP + n]     = __floats2half2_rn(acc[mt][nt][0], acc[mt][nt][1]);
            *(__half2*)&g_Ph[(size_t)(p0 + m + 8) * NP + n] = __floats2half2_rn(acc[mt][nt][2], acc[mt][nt][3]);
        }
    }
}

// ---------------------------------------------------------------------------
// Kernel 2: halo attention. 1024 threads = 32 warps. All-f16 MMA.
// R11 base; O-phase now uses ALL 32 warps (4m x 8n, 8 cols each).
// ---------------------------------------------------------------------------
#define SQP 36
#define SKP 36
#define SVP 72
#define SPP 116
__global__ void __launch_bounds__(1024) k_attn() {
    extern __shared__ uint32_t smu[];
    uint32_t* qsP   = smu;                       // 64*36
    uint32_t* ksP   = qsP + 64 * SQP;            // 224*36 (rows 196..223 zero)
    uint32_t* vsP   = ksP + 224 * SKP;           // 104*72 (j2 98..103 zero)
    uint32_t* psP   = vsP + 104 * SVP;           // 64*116
    float*    rmax  = (float*)(psP + 64 * SPP);  // [8][64]
    float*    rsum  = rmax + 8 * 64;             // [8][64]
    float*    maskv = rsum + 8 * 64;             // [224]

    const int t = threadIdx.x, w = t >> 5, lane = t & 31;
    const int g = lane >> 2, tq = lane & 3;
    const int nb   = blockIdx.x;
    const int head = blockIdx.y;
    const int b    = blockIdx.z;
    const int by = nb >> 4, bx = nb & 15;
    const int qoff = head * 64;
    const int pbase = b * HWH;

    if (t < 224) {
        int j = t;
        bool valid = false;
        if (j < 196) {
            int wy = j / 14, wx = j % 14;
            int gy = by * 8 - 3 + wy, gx = bx * 8 - 3 + wx;
            valid = ((unsigned)gy < 128u) && ((unsigned)gx < 128u);
        }
        maskv[j] = valid ? 1.f : 0.f;
    }
    for (int idx = t; idx < 64 * 16; idx += 1024) {
        int i = idx >> 4, d4 = (idx & 15) * 4;
        int gy = by * 8 + (i >> 3), gx = bx * 8 + (i & 7);
        uint2 v = *(const uint2*)&g_Ph[(size_t)(pbase + gy * 128 + gx) * NP + qoff + d4];
        qsP[i * SQP + (d4 >> 1)]     = v.x;
        qsP[i * SQP + (d4 >> 1) + 1] = v.y;
    }
    {
        __half* vh = (__half*)vsP;
        for (int idx = t; idx < 196 * 16; idx += 1024) {
            int j = idx >> 4, d4 = (idx & 15) * 4;
            int wy = j / 14, wx = j % 14;
            int gy = by * 8 - 3 + wy, gx = bx * 8 - 3 + wx;
            bool valid = ((unsigned)gy < 128u) && ((unsigned)gx < 128u);
            uint2 kv0 = make_uint2(0u, 0u), kv1 = kv0;
            if (valid) {
                size_t base = (size_t)(pbase + gy * 128 + gx) * NP + 512 + qoff + d4;
                kv0 = *(const uint2*)&g_Ph[base];
                kv1 = *(const uint2*)&g_Ph[base + 512];
            }
            ksP[j * SKP + (d4 >> 1)]     = kv0.x;
            ksP[j * SKP + (d4 >> 1) + 1] = kv0.y;
            const __half* pv = (const __half*)&kv1;
            int j2 = j >> 1, ho = j & 1;
            int hb = (j2 * SVP + d4) * 2 + ho;
            vh[hb]     = pv[0];
            vh[hb + 2] = pv[1];
            vh[hb + 4] = pv[2];
            vh[hb + 6] = pv[3];
        }
    }
    for (int idx = t; idx < 28 * SKP; idx += 1024) ksP[196 * SKP + idx] = 0u;
    if (t < 6 * SVP) vsP[98 * SVP + t] = 0u;
    __syncthreads();

    const int m0 = (w & 3) * 16;
    const int nq = w >> 2;
    const int ntiles = nq < 4 ? 4 : 3;
    const int n0q = nq < 4 ? nq * 32 : 128 + (nq - 4) * 24;
    const int rA = m0 + g, rB = rA + 8;

    float sacc[4][4];
    #pragma unroll
    for (int nt = 0; nt < 4; nt++)
        #pragma unroll
        for (int e = 0; e < 4; e++) sacc[nt][e] = 0.f;

    #pragma unroll
    for (int ks16 = 0; ks16 < 4; ks16++) {
        const int k8 = ks16 * 8;
        uint32_t a0 = qsP[rA * SQP + k8 + tq];
        uint32_t a1 = qsP[rB * SQP + k8 + tq];
        uint32_t a2 = qsP[rA * SQP + k8 + tq + 4];
        uint32_t a3 = qsP[rB * SQP + k8 + tq + 4];
        #pragma unroll
        for (int nt = 0; nt < 4; nt++) {
            if (nt < ntiles) {
                int n = n0q + nt * 8 + g;
                uint32_t b0 = ksP[n * SKP + k8 + tq];
                uint32_t b1 = ksP[n * SKP + k8 + tq + 4];
                mma16h(sacc[nt], a0, a1, a2, a3, b0, b1);
            }
        }
    }

    float mA = MAXNEG, mB = MAXNEG;
    #pragma unroll
    for (int nt = 0; nt < 4; nt++) {
        if (nt < ntiles) {
            int jA = n0q + nt * 8 + tq * 2, jB = jA + 1;
            bool vA = maskv[jA] != 0.f, vB = maskv[jB] != 0.f;
            sacc[nt][0] = vA ? sacc[nt][0] : MAXNEG;
            sacc[nt][1] = vB ? sacc[nt][1] : MAXNEG;
            sacc[nt][2] = vA ? sacc[nt][2] : MAXNEG;
            sacc[nt][3] = vB ? sacc[nt][3] : MAXNEG;
            mA = fmaxf(mA, fmaxf(sacc[nt][0], sacc[nt][1]));
            mB = fmaxf(mB, fmaxf(sacc[nt][2], sacc[nt][3]));
        }
    }
    mA = fmaxf(mA, __shfl_xor_sync(0xffffffffu, mA, 1));
    mA = fmaxf(mA, __shfl_xor_sync(0xffffffffu, mA, 2));
    mB = fmaxf(mB, __shfl_xor_sync(0xffffffffu, mB, 1));
    mB = fmaxf(mB, __shfl_xor_sync(0xffffffffu, mB, 2));
    if (tq == 0) { rmax[nq * 64 + rA] = mA; rmax[nq * 64 + rB] = mB; }
    __syncthreads();

    float gmA = MAXNEG, gmB = MAXNEG;
    #pragma unroll
    for (int q = 0; q < 8; q++) {
        gmA = fmaxf(gmA, rmax[q * 64 + rA]);
        gmB = fmaxf(gmB, rmax[q * 64 + rB]);
    }

    float sumA = 0.f, sumB = 0.f;
    #pragma unroll
    for (int nt = 0; nt < 4; nt++) {
        if (nt < ntiles) {
            float eA0 = __expf(sacc[nt][0] - gmA), eA1 = __expf(sacc[nt][1] - gmA);
            float eB0 = __expf(sacc[nt][2] - gmB), eB1 = __expf(sacc[nt][3] - gmB);
            sumA += eA0 + eA1; sumB += eB0 + eB1;
            int c = (n0q >> 1) + nt * 4 + tq;
            psP[rA * SPP + c] = packh2(eA0, eA1);
            psP[rB * SPP + c] = packh2(eB0, eB1);
        }
    }
    sumA += __shfl_xor_sync(0xffffffffu, sumA, 1);
    sumA += __shfl_xor_sync(0xffffffffu, sumA, 2);
    sumB += __shfl_xor_sync(0xffffffffu, sumB, 1);
    sumB += __shfl_xor_sync(0xffffffffu, sumB, 2);
    if (tq == 0) { rsum[nq * 64 + rA] = sumA; rsum[nq * 64 + rB] = sumB; }
    __syncthreads();

    // ---- O = P @ V (f16 m16n8k16), ALL 32 warps: 4m x 8n (8 cols each) ----
    {
        const int m0o = (w & 3) * 16;
        const int n0o = (w >> 2) * 8;
        const int rA2 = m0o + g, rB2 = rA2 + 8;
        float oacc[4];
        #pragma unroll
        for (int e = 0; e < 4; e++) oacc[e] = 0.f;

        #pragma unroll
        for (int k13 = 0; k13 < 13; k13++) {
            const int k2 = k13 * 8;
            uint32_t a0 = psP[rA2 * SPP + k2 + tq];
            uint32_t a1 = psP[rB2 * SPP + k2 + tq];
            uint32_t a2 = psP[rA2 * SPP + k2 + 4 + tq];
            uint32_t a3 = psP[rB2 * SPP + k2 + 4 + tq];
            int n = n0o + g;
            uint32_t b0 = vsP[(k2 + tq) * SVP + n];
            uint32_t b1 = vsP[(k2 + 4 + tq) * SVP + n];
            mma16h(oacc, a0, a1, a2, a3, b0, b1);
        }
        float sA = 0.f, sB = 0.f;
        #pragma unroll
        for (int q = 0; q < 8; q++) {
            sA += rsum[q * 64 + rA2];
            sB += rsum[q * 64 + rB2];
        }
        float invA = 1.0f / sA, invB = 1.0f / sB;
        const int gyA = by * 8 + (rA2 >> 3), gxA = bx * 8 + (rA2 & 7);
        const int gyB = by * 8 + (rB2 >> 3), gxB = bx * 8 + (rB2 & 7);
        __half* dstA = &g_AOh[(size_t)(pbase + gyA * 128 + gxA) * INNER + qoff];
        __half* dstB = &g_AOh[(size_t)(pbase + gyB * 128 + gxB) * INNER + qoff];
        int n = n0o + tq * 2;
        *(__half2*)&dstA[n] = __floats2half2_rn(oacc[0] * invA, oacc[1] * invA);
        *(__half2*)&dstB[n] = __floats2half2_rn(oacc[2] * invB, oacc[3] * invB);
    }
}

// ---------------------------------------------------------------------------
// Kernel 3: out = AO(fp16) @ Wo + bo. f16 MMA + ldmatrix. (unchanged from R11)
// ---------------------------------------------------------------------------
#define SAP 36
__global__ void __launch_bounds__(256) k_out(const float* __restrict__ Wo,
                                             const float* __restrict__ bo,
                                             float* __restrict__ out) {
    extern __shared__ uint32_t smu[];
    uint32_t* AsP = smu;                          // [128][36]
    __half*   Bh  = (__half*)(smu + 128 * SAP);   // [64][136]

    const int t = threadIdx.x, w = t >> 5, lane = t & 31;
    const int qsel = lane >> 3, rsel = lane & 7;
    const int g = lane >> 2, tq = lane & 3;
    const int m0w = (w & 1) * 64, n0w = (w >> 1) * 32;
    const int p0 = blockIdx.x * 128;
    const int b  = p0 >> 14;
    const int y  = (p0 & (HWH - 1)) >> 7;

    float acc[4][4][4];
    #pragma unroll
    for (int mt = 0; mt < 4; mt++)
        #pragma unroll
        for (int nt = 0; nt < 4; nt++)
            #pragma unroll
            for (int e = 0; e < 4; e++) acc[mt][nt][e] = 0.f;

    const uint32_t aB = (uint32_t)__cvta_generic_to_shared(AsP);
    const uint32_t bB = (uint32_t)__cvta_generic_to_shared(Bh);

    for (int kc = 0; kc < 8; kc++) {
        const int K0 = kc * 64;
        __syncthreads();
        for (int idx = t; idx < 128 * 16; idx += 256) {
            int m = idx >> 4, kk = (idx & 15) * 2;
            uint2 v = *(const uint2*)&g_AOh[(size_t)(p0 + m) * INNER + K0 + kk * 2];
            AsP[m * SAP + kk]     = v.x;
            AsP[m * SAP + kk + 1] = v.y;
        }
        for (int idx = t; idx < 64 * 32; idx += 256) {
            int k = idx >> 5, n4 = (idx & 31) * 4;
            float4 v = *(const float4*)&Wo[(size_t)(K0 + k) * CC + n4];
            uint2 hv;
            hv.x = packh2(v.x, v.y);
            hv.y = packh2(v.z, v.w);
            *(uint2*)&Bh[k * SH1 + n4] = hv;
        }
        __syncthreads();

        #pragma unroll
        for (int ks16 = 0; ks16 < 4; ks16++) {
            const int k0 = ks16 * 16;
            const int khA = k0 + (qsel >> 1) * 8;
            uint32_t af[4][4];
            #pragma unroll
            for (int mt = 0; mt < 4; mt++) {
                int m = m0w + mt * 16 + (qsel & 1) * 8 + rsel;
                ldsm4(af[mt], aB + (uint32_t)(m * SAP * 4 + khA * 2));
            }
            const int kkB = k0 + (qsel & 1) * 8 + rsel;
            uint32_t bf[4][2];
            #pragma unroll
            for (int h = 0; h < 2; h++) {
                int n = n0w + h * 16 + (qsel >> 1) * 8;
                uint32_t r4[4];
                ldsm4t(r4, bB + (uint32_t)((kkB * SH1 + n) * 2));
                bf[2 * h][0] = r4[0]; bf[2 * h][1] = r4[1];
                bf[2 * h + 1][0] = r4[2]; bf[2 * h + 1][1] = r4[3];
            }
            #pragma unroll
            for (int nt = 0; nt < 4; nt++)
                #pragma unroll
                for (int mt = 0; mt < 4; mt++)
                    mma16h(acc[mt][nt], af[mt][0], af[mt][1], af[mt][2], af[mt][3],
                           bf[nt][0], bf[nt][1]);
        }
    }

    #pragma unroll
    for (int nt = 0; nt < 4; nt++) {
        int nA = n0w + nt * 8 + tq * 2, nB = nA + 1;
        float biasA = bo[nA], biasB = bo[nB];
        float* colA = out + (size_t)(b * CC + nA) * HWH + y * 128;
        float* colB = out + (size_t)(b * CC + nB) * HWH + y * 128;
        #pragma unroll
        for (int mt = 0; mt < 4; mt++) {
            int m = m0w + mt * 16 + g;
            colA[m]     = acc[mt][nt][0] + biasA;
            colB[m]     = acc[mt][nt][1] + biasB;
            colA[m + 8] = acc[mt][nt][2] + biasA;
            colB[m + 8] = acc[mt][nt][3] + biasB;
        }
    }
}

extern "C" void kernel_launch(void* const* d_in, const int* in_sizes, int n_in,
                              void* d_out, int out_size) {
    const float* x   = (const float*)d_in[0];
    const float* Wq  = (const float*)d_in[1];
    const float* Wkv = (const float*)d_in[2];
    const float* Wo  = (const float*)d_in[3];
    const float* bo  = (const float*)d_in[4];
    float* out = (float*)d_out;

    const int smem1 = 2 * 64 * SH1 * 2;                                  // 34816
    const int smem2 = (64 * SQP + 224 * SKP + 104 * SVP + 64 * SPP
                       + 8 * 64 * 2 + 224) * 4;                          // 106112
    const int smem3 = 128 * SAP * 4 + 64 * SH1 * 2;                      // 35840

    cudaFuncSetAttribute(k_proj, cudaFuncAttributeMaxDynamicSharedMemorySize, smem1);
    cudaFuncSetAttribute(k_attn, cudaFuncAttributeMaxDynamicSharedMemorySize, smem2);
    cudaFuncSetAttribute(k_out,  cudaFuncAttributeMaxDynamicSharedMemorySize, smem3);

    dim3 g1(12, 512);
    k_proj<<<g1, 256, smem1>>>(x, Wq, Wkv);

    dim3 g2(256, 8, 4);
    k_attn<<<g2, 1024, smem2>>>();

    dim3 g3(512);
    k_out<<<g3, 256, smem3>>>(Wo, bo, out);
}

// round 15
// speedup vs baseline: 1.0627x; 1.0627x over previous
#include <cuda_runtime.h>
#include <cuda_fp16.h>
#include <stdint.h>
#include <math.h>

#define BB 4
#define CC 128
#define HWH 16384
#define NPIX 65536
#define INNER 512
#define NP 1536
#define MAXNEG -3.402823466e38f

// fp16 scratch (10-bit mantissa == tf32 mantissa; like-for-like rounding)
__device__ __half g_Ph[(size_t)NPIX * NP];     // [q(512, pre-scaled) | k(512) | v(512)]
__device__ __half g_AOh[(size_t)NPIX * INNER];

__device__ __forceinline__ void mma16h(float* c,
                                       uint32_t a0, uint32_t a1, uint32_t a2, uint32_t a3,
                                       uint32_t b0, uint32_t b1) {
    asm volatile("mma.sync.aligned.m16n8k16.row.col.f32.f16.f16.f32 "
        "{%0,%1,%2,%3}, {%4,%5,%6,%7}, {%8,%9}, {%0,%1,%2,%3};"
        : "+f"(c[0]), "+f"(c[1]), "+f"(c[2]), "+f"(c[3])
        : "r"(a0), "r"(a1), "r"(a2), "r"(a3), "r"(b0), "r"(b1));
}
__device__ __forceinline__ uint32_t packh2(float lo, float hi) {
    __half2 h = __floats2half2_rn(lo, hi);
    return *(uint32_t*)&h;
}
__device__ __forceinline__ void ldsm4(uint32_t* r, uint32_t addr) {
    asm volatile("ldmatrix.sync.aligned.m8n8.x4.shared.b16 {%0,%1,%2,%3}, [%4];"
        : "=r"(r[0]), "=r"(r[1]), "=r"(r[2]), "=r"(r[3]) : "r"(addr));
}
__device__ __forceinline__ void ldsm4t(uint32_t* r, uint32_t addr) {
    asm volatile("ldmatrix.sync.aligned.m8n8.x4.trans.shared.b16 {%0,%1,%2,%3}, [%4];"
        : "=r"(r[0]), "=r"(r[1]), "=r"(r[2]), "=r"(r[3]) : "r"(addr));
}

// ---------------------------------------------------------------------------
// Kernel 1: P[p,:] = x_pixel[p,:] @ [Wq*0.125 | Wkv].  f16 MMA + ldmatrix.
// (exact R11 version — proven 218us, 2 CTAs/SM)
// ---------------------------------------------------------------------------
#define SH1 136
__global__ void __launch_bounds__(256) k_proj(const float* __restrict__ x,
                                              const float* __restrict__ Wq,
                                              const float* __restrict__ Wkv) {
    extern __shared__ __half smh[];
    __half* Ah = smh;              // [64][136]
    __half* Bh = smh + 64 * SH1;   // [64][136]

    const int t = threadIdx.x, w = t >> 5, lane = t & 31;
    const int qsel = lane >> 3, rsel = lane & 7;
    const int g = lane >> 2, tq = lane & 3;
    const int m0w = (w & 1) * 64, n0w = (w >> 1) * 32;
    const int jt = blockIdx.x;                 // 0..3 Wq, 4..11 Wkv
    const int p0 = blockIdx.y * 128;
    const int b  = p0 >> 14;
    const int y  = (p0 & (HWH - 1)) >> 7;

    float acc[4][4][4];
    #pragma unroll
    for (int mt = 0; mt < 4; mt++)
        #pragma unroll
        for (int nt = 0; nt < 4; nt++)
            #pragma unroll
            for (int e = 0; e < 4; e++) acc[mt][nt][e] = 0.f;

    const uint32_t aB = (uint32_t)__cvta_generic_to_shared(Ah);
    const uint32_t bB = (uint32_t)__cvta_generic_to_shared(Bh);

    for (int kc = 0; kc < 2; kc++) {
        const int K0 = kc * 64;
        __syncthreads();
        const float* xb = x + ((size_t)(b * CC + K0) * 128 + y) * 128;
        for (int idx = t; idx < 64 * 32; idx += 256) {
            int k = idx >> 5, m4 = (idx & 31) * 4;
            float4 v = *(const float4*)(xb + (size_t)k * HWH + m4);
            uint2 hv;
            hv.x = packh2(v.x, v.y);
            hv.y = packh2(v.z, v.w);
            *(uint2*)&Ah[k * SH1 + m4] = hv;
        }
        if (jt < 4) {
            const float* Wb = Wq + (size_t)K0 * INNER + jt * 128;
            for (int idx = t; idx < 64 * 32; idx += 256) {
                int k = idx >> 5, n4 = (idx & 31) * 4;
                float4 v = *(const float4*)(Wb + (size_t)k * INNER + n4);
                uint2 hv;
                hv.x = packh2(v.x * 0.125f, v.y * 0.125f);
                hv.y = packh2(v.z * 0.125f, v.w * 0.125f);
                *(uint2*)&Bh[k * SH1 + n4] = hv;
            }
        } else {
            const float* Wb = Wkv + (size_t)K0 * 1024 + (jt - 4) * 128;
            for (int idx = t; idx < 64 * 32; idx += 256) {
                int k = idx >> 5, n4 = (idx & 31) * 4;
                float4 v = *(const float4*)(Wb + (size_t)k * 1024 + n4);
                uint2 hv;
                hv.x = packh2(v.x, v.y);
                hv.y = packh2(v.z, v.w);
                *(uint2*)&Bh[k * SH1 + n4] = hv;
            }
        }
        __syncthreads();

        #pragma unroll
        for (int ks16 = 0; ks16 < 4; ks16++) {
            const int k0 = ks16 * 16;
            const int kkA = k0 + (qsel >> 1) * 8 + rsel;
            uint32_t af[4][4];
            #pragma unroll
            for (int mt = 0; mt < 4; mt++) {
                int m = m0w + mt * 16 + (qsel & 1) * 8;
                ldsm4t(af[mt], aB + (uint32_t)((kkA * SH1 + m) * 2));
            }
            const int kkB = k0 + (qsel & 1) * 8 + rsel;
            uint32_t bf[4][2];
            #pragma unroll
            for (int h = 0; h < 2; h++) {
                int n = n0w + h * 16 + (qsel >> 1) * 8;
                uint32_t r4[4];
                ldsm4t(r4, bB + (uint32_t)((kkB * SH1 + n) * 2));
                bf[2 * h][0] = r4[0]; bf[2 * h][1] = r4[1];
                bf[2 * h + 1][0] = r4[2]; bf[2 * h + 1][1] = r4[3];
            }
            #pragma unroll
            for (int nt = 0; nt < 4; nt++)
                #pragma unroll
                for (int mt = 0; mt < 4; mt++)
                    mma16h(acc[mt][nt], af[mt][0], af[mt][1], af[mt][2], af[mt][3],
                           bf[nt][0], bf[nt][1]);
        }
    }

    const int colb = jt * 128;
    #pragma unroll
    for (int mt = 0; mt < 4; mt++) {
        int m = m0w + mt * 16 + g;
        #pragma unroll
        for (int nt = 0; nt < 4; nt++) {
            int n = colb + n0w + nt * 8 + tq * 2;
            *(__half2*)&g_Ph[(size_t)(p0 + m) * NP + n]     = __floats2half2_rn(acc[mt][nt][0], acc[mt][nt][1]);
            *(__half2*)&g_Ph[(size_t)(p0 + m + 8) * NP + n] = __floats2half2_rn(acc[mt][nt][2], acc[mt][nt][3]);
        }
    }
}

// ---------------------------------------------------------------------------
// Kernel 2: halo attention. 1024 threads = 32 warps. All-f16 MMA.
// R11 structure; S-phase and O-phase A fragment loads via ldmatrix (fewer
// LDS issues, same bytes / layouts / warp mapping).
// ---------------------------------------------------------------------------
#define SQP 36
#define SKP 36
#define SVP 72
#define SPP 116
__global__ void __launch_bounds__(1024) k_attn() {
    extern __shared__ uint32_t smu[];
    uint32_t* qsP   = smu;                       // 64*36
    uint32_t* ksP   = qsP + 64 * SQP;            // 224*36 (rows 196..223 zero)
    uint32_t* vsP   = ksP + 224 * SKP;           // 104*72 (j2 98..103 zero)
    uint32_t* psP   = vsP + 104 * SVP;           // 64*116
    float*    rmax  = (float*)(psP + 64 * SPP);  // [8][64]
    float*    rsum  = rmax + 8 * 64;             // [8][64]
    float*    maskv = rsum + 8 * 64;             // [224]

    const int t = threadIdx.x, w = t >> 5, lane = t & 31;
    const int qsel = lane >> 3, rsel = lane & 7;
    const int g = lane >> 2, tq = lane & 3;
    const int nb   = blockIdx.x;
    const int head = blockIdx.y;
    const int b    = blockIdx.z;
    const int by = nb >> 4, bx = nb & 15;
    const int qoff = head * 64;
    const int pbase = b * HWH;

    const uint32_t qB = (uint32_t)__cvta_generic_to_shared(qsP);
    const uint32_t kB = (uint32_t)__cvta_generic_to_shared(ksP);
    const uint32_t pB = (uint32_t)__cvta_generic_to_shared(psP);

    if (t < 224) {
        int j = t;
        bool valid = false;
        if (j < 196) {
            int wy = j / 14, wx = j % 14;
            int gy = by * 8 - 3 + wy, gx = bx * 8 - 3 + wx;
            valid = ((unsigned)gy < 128u) && ((unsigned)gx < 128u);
        }
        maskv[j] = valid ? 1.f : 0.f;
    }
    for (int idx = t; idx < 64 * 16; idx += 1024) {
        int i = idx >> 4, d4 = (idx & 15) * 4;
        int gy = by * 8 + (i >> 3), gx = bx * 8 + (i & 7);
        uint2 v = *(const uint2*)&g_Ph[(size_t)(pbase + gy * 128 + gx) * NP + qoff + d4];
        qsP[i * SQP + (d4 >> 1)]     = v.x;
        qsP[i * SQP + (d4 >> 1) + 1] = v.y;
    }
    {
        __half* vh = (__half*)vsP;
        for (int idx = t; idx < 196 * 16; idx += 1024) {
            int j = idx >> 4, d4 = (idx & 15) * 4;
            int wy = j / 14, wx = j % 14;
            int gy = by * 8 - 3 + wy, gx = bx * 8 - 3 + wx;
            bool valid = ((unsigned)gy < 128u) && ((unsigned)gx < 128u);
            uint2 kv0 = make_uint2(0u, 0u), kv1 = kv0;
            if (valid) {
                size_t base = (size_t)(pbase + gy * 128 + gx) * NP + 512 + qoff + d4;
                kv0 = *(const uint2*)&g_Ph[base];
                kv1 = *(const uint2*)&g_Ph[base + 512];
            }
            ksP[j * SKP + (d4 >> 1)]     = kv0.x;
            ksP[j * SKP + (d4 >> 1) + 1] = kv0.y;
            const __half* pv = (const __half*)&kv1;
            int j2 = j >> 1, ho = j & 1;
            int hb = (j2 * SVP + d4) * 2 + ho;
            vh[hb]     = pv[0];
            vh[hb + 2] = pv[1];
            vh[hb + 4] = pv[2];
            vh[hb + 6] = pv[3];
        }
    }
    for (int idx = t; idx < 28 * SKP; idx += 1024) ksP[196 * SKP + idx] = 0u;
    if (t < 6 * SVP) vsP[98 * SVP + t] = 0u;
    __syncthreads();

    const int m0 = (w & 3) * 16;
    const int nq = w >> 2;
    const int ntiles = nq < 4 ? 4 : 3;
    const int n0q = nq < 4 ? nq * 32 : 128 + (nq - 4) * 24;
    const int rA = m0 + g, rB = rA + 8;

    float sacc[4][4];
    #pragma unroll
    for (int nt = 0; nt < 4; nt++)
        #pragma unroll
        for (int e = 0; e < 4; e++) sacc[nt][e] = 0.f;

    #pragma unroll
    for (int ks16 = 0; ks16 < 4; ks16++) {
        const int k8 = ks16 * 8;
        // A frags via ldmatrix: rows m0..m0+15, k-halves 2*k8..; lane->[m0+g][k8+tq]
        uint32_t af[4];
        ldsm4(af, qB + (uint32_t)(((m0 + (qsel & 1) * 8 + rsel) * SQP + k8 + (qsel >> 1) * 4) * 4));
        // B frags via ldmatrix: 2 n-tiles per x4; r0=b0(t0) r1=b1(t0) r2=b0(t1) r3=b1(t1)
        uint32_t bf[4][2];
        #pragma unroll
        for (int h = 0; h < 2; h++) {
            int nb0 = n0q + h * 16;
            uint32_t r4[4];
            ldsm4(r4, kB + (uint32_t)(((nb0 + (qsel >> 1) * 8 + rsel) * SKP + k8 + (qsel & 1) * 4) * 4));
            bf[2 * h][0] = r4[0]; bf[2 * h][1] = r4[1];
            bf[2 * h + 1][0] = r4[2]; bf[2 * h + 1][1] = r4[3];
        }
        #pragma unroll
        for (int nt = 0; nt < 4; nt++) {
            if (nt < ntiles)
                mma16h(sacc[nt], af[0], af[1], af[2], af[3], bf[nt][0], bf[nt][1]);
        }
    }

    float mA = MAXNEG, mB = MAXNEG;
    #pragma unroll
    for (int nt = 0; nt < 4; nt++) {
        if (nt < ntiles) {
            int jA = n0q + nt * 8 + tq * 2, jB = jA + 1;
            bool vA = maskv[jA] != 0.f, vB = maskv[jB] != 0.f;
            sacc[nt][0] = vA ? sacc[nt][0] : MAXNEG;
            sacc[nt][1] = vB ? sacc[nt][1] : MAXNEG;
            sacc[nt][2] = vA ? sacc[nt][2] : MAXNEG;
            sacc[nt][3] = vB ? sacc[nt][3] : MAXNEG;
            mA = fmaxf(mA, fmaxf(sacc[nt][0], sacc[nt][1]));
            mB = fmaxf(mB, fmaxf(sacc[nt][2], sacc[nt][3]));
        }
    }
    mA = fmaxf(mA, __shfl_xor_sync(0xffffffffu, mA, 1));
    mA = fmaxf(mA, __shfl_xor_sync(0xffffffffu, mA, 2));
    mB = fmaxf(mB, __shfl_xor_sync(0xffffffffu, mB, 1));
    mB = fmaxf(mB, __shfl_xor_sync(0xffffffffu, mB, 2));
    if (tq == 0) { rmax[nq * 64 + rA] = mA; rmax[nq * 64 + rB] = mB; }
    __syncthreads();

    float gmA = MAXNEG, gmB = MAXNEG;
    #pragma unroll
    for (int q = 0; q < 8; q++) {
        gmA = fmaxf(gmA, rmax[q * 64 + rA]);
        gmB = fmaxf(gmB, rmax[q * 64 + rB]);
    }

    float sumA = 0.f, sumB = 0.f;
    #pragma unroll
    for (int nt = 0; nt < 4; nt++) {
        if (nt < ntiles) {
            float eA0 = __expf(sacc[nt][0] - gmA), eA1 = __expf(sacc[nt][1] - gmA);
            float eB0 = __expf(sacc[nt][2] - gmB), eB1 = __expf(sacc[nt][3] - gmB);
            sumA += eA0 + eA1; sumB += eB0 + eB1;
            int c = (n0q >> 1) + nt * 4 + tq;
            psP[rA * SPP + c] = packh2(eA0, eA1);
            psP[rB * SPP + c] = packh2(eB0, eB1);
        }
    }
    sumA += __shfl_xor_sync(0xffffffffu, sumA, 1);
    sumA += __shfl_xor_sync(0xffffffffu, sumA, 2);
    sumB += __shfl_xor_sync(0xffffffffu, sumB, 1);
    sumB += __shfl_xor_sync(0xffffffffu, sumB, 2);
    if (tq == 0) { rsum[nq * 64 + rA] = sumA; rsum[nq * 64 + rB] = sumB; }
    __syncthreads();

    // ---- O = P @ V (f16 m16n8k16), 16 warps: 4m x 4n(16 cols) ----
    if (w < 16) {
        const int m0o = (w & 3) * 16;
        const int n0o = (w >> 2) * 16;
        const int rA2 = m0o + g, rB2 = rA2 + 8;
        float oacc[2][4];
        #pragma unroll
        for (int nt = 0; nt < 2; nt++)
            #pragma unroll
            for (int e = 0; e < 4; e++) oacc[nt][e] = 0.f;

        #pragma unroll
        for (int k13 = 0; k13 < 13; k13++) {
            const int k2 = k13 * 8;
            // A frags via ldmatrix on psP
            uint32_t af[4];
            ldsm4(af, pB + (uint32_t)(((m0o + (qsel & 1) * 8 + rsel) * SPP + k2 + (qsel >> 1) * 4) * 4));
            #pragma unroll
            for (int nt = 0; nt < 2; nt++) {
                int n = n0o + nt * 8 + g;
                uint32_t b0 = vsP[(k2 + tq) * SVP + n];
                uint32_t b1 = vsP[(k2 + 4 + tq) * SVP + n];
                mma16h(oacc[nt], af[0], af[1], af[2], af[3], b0, b1);
            }
        }
        float sA = 0.f, sB = 0.f;
        #pragma unroll
        for (int q = 0; q < 8; q++) {
            sA += rsum[q * 64 + rA2];
            sB += rsum[q * 64 + rB2];
        }
        float invA = 1.0f / sA, invB = 1.0f / sB;
        const int gyA = by * 8 + (rA2 >> 3), gxA = bx * 8 + (rA2 & 7);
        const int gyB = by * 8 + (rB2 >> 3), gxB = bx * 8 + (rB2 & 7);
        __half* dstA = &g_AOh[(size_t)(pbase + gyA * 128 + gxA) * INNER + qoff];
        __half* dstB = &g_AOh[(size_t)(pbase + gyB * 128 + gxB) * INNER + qoff];
        #pragma unroll
        for (int nt = 0; nt < 2; nt++) {
            int n = n0o + nt * 8 + tq * 2;
            *(__half2*)&dstA[n] = __floats2half2_rn(oacc[nt][0] * invA, oacc[nt][1] * invA);
            *(__half2*)&dstB[n] = __floats2half2_rn(oacc[nt][2] * invB, oacc[nt][3] * invB);
        }
    }
}

// ---------------------------------------------------------------------------
// Kernel 3: out = AO(fp16) @ Wo + bo. f16 MMA + ldmatrix. (unchanged from R11)
// ---------------------------------------------------------------------------
#define SAP 36
__global__ void __launch_bounds__(256) k_out(const float* __restrict__ Wo,
                                             const float* __restrict__ bo,
                                             float* __restrict__ out) {
    extern __shared__ uint32_t smu[];
    uint32_t* AsP = smu;                          // [128][36]
    __half*   Bh  = (__half*)(smu + 128 * SAP);   // [64][136]

    const int t = threadIdx.x, w = t >> 5, lane = t & 31;
    const int qsel = lane >> 3, rsel = lane & 7;
    const int g = lane >> 2, tq = lane & 3;
    const int m0w = (w & 1) * 64, n0w = (w >> 1) * 32;
    const int p0 = blockIdx.x * 128;
    const int b  = p0 >> 14;
    const int y  = (p0 & (HWH - 1)) >> 7;

    float acc[4][4][4];
    #pragma unroll
    for (int mt = 0; mt < 4; mt++)
        #pragma unroll
        for (int nt = 0; nt < 4; nt++)
            #pragma unroll
            for (int e = 0; e < 4; e++) acc[mt][nt][e] = 0.f;

    const uint32_t aB = (uint32_t)__cvta_generic_to_shared(AsP);
    const uint32_t bB = (uint32_t)__cvta_generic_to_shared(Bh);

    for (int kc = 0; kc < 8; kc++) {
        const int K0 = kc * 64;
        __syncthreads();
        for (int idx = t; idx < 128 * 16; idx += 256) {
            int m = idx >> 4, kk = (idx & 15) * 2;
            uint2 v = *(const uint2*)&g_AOh[(size_t)(p0 + m) * INNER + K0 + kk * 2];
            AsP[m * SAP + kk]     = v.x;
            AsP[m * SAP + kk + 1] = v.y;
        }
        for (int idx = t; idx < 64 * 32; idx += 256) {
            int k = idx >> 5, n4 = (idx & 31) * 4;
            float4 v = *(const float4*)&Wo[(size_t)(K0 + k) * CC + n4];
            uint2 hv;
            hv.x = packh2(v.x, v.y);
            hv.y = packh2(v.z, v.w);
            *(uint2*)&Bh[k * SH1 + n4] = hv;
        }
        __syncthreads();

        #pragma unroll
        for (int ks16 = 0; ks16 < 4; ks16++) {
            const int k0 = ks16 * 16;
            const int khA = k0 + (qsel >> 1) * 8;
            uint32_t af[4][4];
            #pragma unroll
            for (int mt = 0; mt < 4; mt++) {
                int m = m0w + mt * 16 + (qsel & 1) * 8 + rsel;
                ldsm4(af[mt], aB + (uint32_t)(m * SAP * 4 + khA * 2));
            }
            const int kkB = k0 + (qsel & 1) * 8 + rsel;
            uint32_t bf[4][2];
            #pragma unroll
            for (int h = 0; h < 2; h++) {
                int n = n0w + h * 16 + (qsel >> 1) * 8;
                uint32_t r4[4];
                ldsm4t(r4, bB + (uint32_t)((kkB * SH1 + n) * 2));
                bf[2 * h][0] = r4[0]; bf[2 * h][1] = r4[1];
                bf[2 * h + 1][0] = r4[2]; bf[2 * h + 1][1] = r4[3];
            }
            #pragma unroll
            for (int nt = 0; nt < 4; nt++)
                #pragma unroll
                for (int mt = 0; mt < 4; mt++)
                    mma16h(acc[mt][nt], af[mt][0], af[mt][1], af[mt][2], af[mt][3],
                           bf[nt][0], bf[nt][1]);
        }
    }

    #pragma unroll
    for (int nt = 0; nt < 4; nt++) {
        int nA = n0w + nt * 8 + tq * 2, nB = nA + 1;
        float biasA = bo[nA], biasB = bo[nB];
        float* colA = out + (size_t)(b * CC + nA) * HWH + y * 128;
        float* colB = out + (size_t)(b * CC + nB) * HWH + y * 128;
        #pragma unroll
        for (int mt = 0; mt < 4; mt++) {
            int m = m0w + mt * 16 + g;
            colA[m]     = acc[mt][nt][0] + biasA;
            colB[m]     = acc[mt][nt][1] + biasB;
            colA[m + 8] = acc[mt][nt][2] + biasA;
            colB[m + 8] = acc[mt][nt][3] + biasB;
        }
    }
}

extern "C" void kernel_launch(void* const* d_in, const int* in_sizes, int n_in,
                              void* d_out, int out_size) {
    const float* x   = (const float*)d_in[0];
    const float* Wq  = (const float*)d_in[1];
    const float* Wkv = (const float*)d_in[2];
    const float* Wo  = (const float*)d_in[3];
    const float* bo  = (const float*)d_in[4];
    float* out = (float*)d_out;

    const int smem1 = 2 * 64 * SH1 * 2;                                  // 34816
    const int smem2 = (64 * SQP + 224 * SKP + 104 * SVP + 64 * SPP
                       + 8 * 64 * 2 + 224) * 4;                          // 106112
    const int smem3 = 128 * SAP * 4 + 64 * SH1 * 2;                      // 35840

    cudaFuncSetAttribute(k_proj, cudaFuncAttributeMaxDynamicSharedMemorySize, smem1);
    cudaFuncSetAttribute(k_attn, cudaFuncAttributeMaxDynamicSharedMemorySize, smem2);
    cudaFuncSetAttribute(k_out,  cudaFuncAttributeMaxDynamicSharedMemorySize, smem3);

    dim3 g1(12, 512);
    k_proj<<<g1, 256, smem1>>>(x, Wq, Wkv);

    dim3 g2(256, 8, 4);
    k_attn<<<g2, 1024, smem2>>>();

    dim3 g3(512);
    k_out<<<g3, 256, smem3>>>(Wo, bo, out);
}

// round 16
// speedup vs baseline: 1.2689x; 1.1941x over previous
#include <cuda_runtime.h>
#include <cuda_fp16.h>
#include <stdint.h>
#include <math.h>

#define BB 4
#define CC 128
#define HWH 16384
#define NPIX 65536
#define INNER 512
#define NP 1536
#define MAXNEG -3.402823466e38f

// fp16 scratch (10-bit mantissa == tf32 mantissa; like-for-like rounding)
__device__ __half g_Ph[(size_t)NPIX * NP];     // [q(512, pre-scaled) | k(512) | v(512)]
__device__ __half g_AOh[(size_t)NPIX * INNER];

__device__ __forceinline__ void mma16h(float* c,
                                       uint32_t a0, uint32_t a1, uint32_t a2, uint32_t a3,
                                       uint32_t b0, uint32_t b1) {
    asm volatile("mma.sync.aligned.m16n8k16.row.col.f32.f16.f16.f32 "
        "{%0,%1,%2,%3}, {%4,%5,%6,%7}, {%8,%9}, {%0,%1,%2,%3};"
        : "+f"(c[0]), "+f"(c[1]), "+f"(c[2]), "+f"(c[3])
        : "r"(a0), "r"(a1), "r"(a2), "r"(a3), "r"(b0), "r"(b1));
}
__device__ __forceinline__ uint32_t packh2(float lo, float hi) {
    __half2 h = __floats2half2_rn(lo, hi);
    return *(uint32_t*)&h;
}
__device__ __forceinline__ void ldsm4(uint32_t* r, uint32_t addr) {
    asm volatile("ldmatrix.sync.aligned.m8n8.x4.shared.b16 {%0,%1,%2,%3}, [%4];"
        : "=r"(r[0]), "=r"(r[1]), "=r"(r[2]), "=r"(r[3]) : "r"(addr));
}
__device__ __forceinline__ void ldsm4t(uint32_t* r, uint32_t addr) {
    asm volatile("ldmatrix.sync.aligned.m8n8.x4.trans.shared.b16 {%0,%1,%2,%3}, [%4];"
        : "=r"(r[0]), "=r"(r[1]), "=r"(r[2]), "=r"(r[3]) : "r"(addr));
}

// ---------------------------------------------------------------------------
// Kernel 1: P[p,:] = x_pixel[p,:] @ [Wq*0.125 | Wkv].  f16 MMA + ldmatrix.
// 512 threads = 16 warps (4m x 4n), warp tile 32x32 -> acc 32 regs,
// __launch_bounds__(512,2) targets 2 CTAs/SM (32 warps/SM).
// smem: Ah half[64][136] + Bh half[64][136] = 34816 B.
// ---------------------------------------------------------------------------
#define SH1 136
__global__ void __launch_bounds__(512, 2) k_proj(const float* __restrict__ x,
                                                 const float* __restrict__ Wq,
                                                 const float* __restrict__ Wkv) {
    extern __shared__ __half smh[];
    __half* Ah = smh;              // [64][136]
    __half* Bh = smh + 64 * SH1;   // [64][136]

    const int t = threadIdx.x, w = t >> 5, lane = t & 31;
    const int qsel = lane >> 3, rsel = lane & 7;
    const int g = lane >> 2, tq = lane & 3;
    const int m0w = (w & 3) * 32, n0w = (w >> 2) * 32;
    const int jt = blockIdx.x;                 // 0..3 Wq, 4..11 Wkv
    const int p0 = blockIdx.y * 128;
    const int b  = p0 >> 14;
    const int y  = (p0 & (HWH - 1)) >> 7;

    float acc[2][4][4];
    #pragma unroll
    for (int mt = 0; mt < 2; mt++)
        #pragma unroll
        for (int nt = 0; nt < 4; nt++)
            #pragma unroll
            for (int e = 0; e < 4; e++) acc[mt][nt][e] = 0.f;

    const uint32_t aB = (uint32_t)__cvta_generic_to_shared(Ah);
    const uint32_t bB = (uint32_t)__cvta_generic_to_shared(Bh);

    for (int kc = 0; kc < 2; kc++) {
        const int K0 = kc * 64;
        __syncthreads();
        const float* xb = x + ((size_t)(b * CC + K0) * 128 + y) * 128;
        for (int idx = t; idx < 64 * 32; idx += 512) {
            int k = idx >> 5, m4 = (idx & 31) * 4;
            float4 v = *(const float4*)(xb + (size_t)k * HWH + m4);
            uint2 hv;
            hv.x = packh2(v.x, v.y);
            hv.y = packh2(v.z, v.w);
            *(uint2*)&Ah[k * SH1 + m4] = hv;
        }
        if (jt < 4) {
            const float* Wb = Wq + (size_t)K0 * INNER + jt * 128;
            for (int idx = t; idx < 64 * 32; idx += 512) {
                int k = idx >> 5, n4 = (idx & 31) * 4;
                float4 v = *(const float4*)(Wb + (size_t)k * INNER + n4);
                uint2 hv;
                hv.x = packh2(v.x * 0.125f, v.y * 0.125f);
                hv.y = packh2(v.z * 0.125f, v.w * 0.125f);
                *(uint2*)&Bh[k * SH1 + n4] = hv;
            }
        } else {
            const float* Wb = Wkv + (size_t)K0 * 1024 + (jt - 4) * 128;
            for (int idx = t; idx < 64 * 32; idx += 512) {
                int k = idx >> 5, n4 = (idx & 31) * 4;
                float4 v = *(const float4*)(Wb + (size_t)k * 1024 + n4);
                uint2 hv;
                hv.x = packh2(v.x, v.y);
                hv.y = packh2(v.z, v.w);
                *(uint2*)&Bh[k * SH1 + n4] = hv;
            }
        }
        __syncthreads();

        #pragma unroll
        for (int ks16 = 0; ks16 < 4; ks16++) {
            const int k0 = ks16 * 16;
            // A fragments: 2 m-tiles via ldmatrix.x4.trans
            const int kkA = k0 + (qsel >> 1) * 8 + rsel;
            uint32_t af[2][4];
            #pragma unroll
            for (int mt = 0; mt < 2; mt++) {
                int m = m0w + mt * 16 + (qsel & 1) * 8;
                ldsm4t(af[mt], aB + (uint32_t)((kkA * SH1 + m) * 2));
            }
            // B fragments: 4 n-tiles via 2 ldmatrix.x4.trans
            const int kkB = k0 + (qsel & 1) * 8 + rsel;
            uint32_t bf[4][2];
            #pragma unroll
            for (int h = 0; h < 2; h++) {
                int n = n0w + h * 16 + (qsel >> 1) * 8;
                uint32_t r4[4];
                ldsm4t(r4, bB + (uint32_t)((kkB * SH1 + n) * 2));
                bf[2 * h][0] = r4[0]; bf[2 * h][1] = r4[1];
                bf[2 * h + 1][0] = r4[2]; bf[2 * h + 1][1] = r4[3];
            }
            #pragma unroll
            for (int nt = 0; nt < 4; nt++)
                #pragma unroll
                for (int mt = 0; mt < 2; mt++)
                    mma16h(acc[mt][nt], af[mt][0], af[mt][1], af[mt][2], af[mt][3],
                           bf[nt][0], bf[nt][1]);
        }
    }

    const int colb = jt * 128;
    #pragma unroll
    for (int mt = 0; mt < 2; mt++) {
        int m = m0w + mt * 16 + g;
        #pragma unroll
        for (int nt = 0; nt < 4; nt++) {
            int n = colb + n0w + nt * 8 + tq * 2;
            *(__half2*)&g_Ph[(size_t)(p0 + m) * NP + n]     = __floats2half2_rn(acc[mt][nt][0], acc[mt][nt][1]);
            *(__half2*)&g_Ph[(size_t)(p0 + m + 8) * NP + n] = __floats2half2_rn(acc[mt][nt][2], acc[mt][nt][3]);
        }
    }
}

// ---------------------------------------------------------------------------
// Kernel 2: halo attention. 1024 threads = 32 warps. All-f16 MMA.
// (exact R11 version — proven local optimum)
// ---------------------------------------------------------------------------
#define SQP 36
#define SKP 36
#define SVP 72
#define SPP 116
__global__ void __launch_bounds__(1024) k_attn() {
    extern __shared__ uint32_t smu[];
    uint32_t* qsP   = smu;                       // 64*36
    uint32_t* ksP   = qsP + 64 * SQP;            // 224*36 (rows 196..223 zero)
    uint32_t* vsP   = ksP + 224 * SKP;           // 104*72 (j2 98..103 zero)
    uint32_t* psP   = vsP + 104 * SVP;           // 64*116
    float*    rmax  = (float*)(psP + 64 * SPP);  // [8][64]
    float*    rsum  = rmax + 8 * 64;             // [8][64]
    float*    maskv = rsum + 8 * 64;             // [224]

    const int t = threadIdx.x, w = t >> 5, lane = t & 31;
    const int g = lane >> 2, tq = lane & 3;
    const int nb   = blockIdx.x;
    const int head = blockIdx.y;
    const int b    = blockIdx.z;
    const int by = nb >> 4, bx = nb & 15;
    const int qoff = head * 64;
    const int pbase = b * HWH;

    if (t < 224) {
        int j = t;
        bool valid = false;
        if (j < 196) {
            int wy = j / 14, wx = j % 14;
            int gy = by * 8 - 3 + wy, gx = bx * 8 - 3 + wx;
            valid = ((unsigned)gy < 128u) && ((unsigned)gx < 128u);
        }
        maskv[j] = valid ? 1.f : 0.f;
    }
    for (int idx = t; idx < 64 * 16; idx += 1024) {
        int i = idx >> 4, d4 = (idx & 15) * 4;
        int gy = by * 8 + (i >> 3), gx = bx * 8 + (i & 7);
        uint2 v = *(const uint2*)&g_Ph[(size_t)(pbase + gy * 128 + gx) * NP + qoff + d4];
        qsP[i * SQP + (d4 >> 1)]     = v.x;
        qsP[i * SQP + (d4 >> 1) + 1] = v.y;
    }
    {
        __half* vh = (__half*)vsP;
        for (int idx = t; idx < 196 * 16; idx += 1024) {
            int j = idx >> 4, d4 = (idx & 15) * 4;
            int wy = j / 14, wx = j % 14;
            int gy = by * 8 - 3 + wy, gx = bx * 8 - 3 + wx;
            bool valid = ((unsigned)gy < 128u) && ((unsigned)gx < 128u);
            uint2 kv0 = make_uint2(0u, 0u), kv1 = kv0;
            if (valid) {
                size_t base = (size_t)(pbase + gy * 128 + gx) * NP + 512 + qoff + d4;
                kv0 = *(const uint2*)&g_Ph[base];
                kv1 = *(const uint2*)&g_Ph[base + 512];
            }
            ksP[j * SKP + (d4 >> 1)]     = kv0.x;
            ksP[j * SKP + (d4 >> 1) + 1] = kv0.y;
            const __half* pv = (const __half*)&kv1;
            int j2 = j >> 1, ho = j & 1;
            int hb = (j2 * SVP + d4) * 2 + ho;
            vh[hb]     = pv[0];
            vh[hb + 2] = pv[1];
            vh[hb + 4] = pv[2];
            vh[hb + 6] = pv[3];
        }
    }
    for (int idx = t; idx < 28 * SKP; idx += 1024) ksP[196 * SKP + idx] = 0u;
    if (t < 6 * SVP) vsP[98 * SVP + t] = 0u;
    __syncthreads();

    const int m0 = (w & 3) * 16;
    const int nq = w >> 2;
    const int ntiles = nq < 4 ? 4 : 3;
    const int n0q = nq < 4 ? nq * 32 : 128 + (nq - 4) * 24;
    const int rA = m0 + g, rB = rA + 8;

    float sacc[4][4];
    #pragma unroll
    for (int nt = 0; nt < 4; nt++)
        #pragma unroll
        for (int e = 0; e < 4; e++) sacc[nt][e] = 0.f;

    #pragma unroll
    for (int ks16 = 0; ks16 < 4; ks16++) {
        const int k8 = ks16 * 8;
        uint32_t a0 = qsP[rA * SQP + k8 + tq];
        uint32_t a1 = qsP[rB * SQP + k8 + tq];
        uint32_t a2 = qsP[rA * SQP + k8 + tq + 4];
        uint32_t a3 = qsP[rB * SQP + k8 + tq + 4];
        #pragma unroll
        for (int nt = 0; nt < 4; nt++) {
            if (nt < ntiles) {
                int n = n0q + nt * 8 + g;
                uint32_t b0 = ksP[n * SKP + k8 + tq];
                uint32_t b1 = ksP[n * SKP + k8 + tq + 4];
                mma16h(sacc[nt], a0, a1, a2, a3, b0, b1);
            }
        }
    }

    float mA = MAXNEG, mB = MAXNEG;
    #pragma unroll
    for (int nt = 0; nt < 4; nt++) {
        if (nt < ntiles) {
            int jA = n0q + nt * 8 + tq * 2, jB = jA + 1;
            bool vA = maskv[jA] != 0.f, vB = maskv[jB] != 0.f;
            sacc[nt][0] = vA ? sacc[nt][0] : MAXNEG;
            sacc[nt][1] = vB ? sacc[nt][1] : MAXNEG;
            sacc[nt][2] = vA ? sacc[nt][2] : MAXNEG;
            sacc[nt][3] = vB ? sacc[nt][3] : MAXNEG;
            mA = fmaxf(mA, fmaxf(sacc[nt][0], sacc[nt][1]));
            mB = fmaxf(mB, fmaxf(sacc[nt][2], sacc[nt][3]));
        }
    }
    mA = fmaxf(mA, __shfl_xor_sync(0xffffffffu, mA, 1));
    mA = fmaxf(mA, __shfl_xor_sync(0xffffffffu, mA, 2));
    mB = fmaxf(mB, __shfl_xor_sync(0xffffffffu, mB, 1));
    mB = fmaxf(mB, __shfl_xor_sync(0xffffffffu, mB, 2));
    if (tq == 0) { rmax[nq * 64 + rA] = mA; rmax[nq * 64 + rB] = mB; }
    __syncthreads();

    float gmA = MAXNEG, gmB = MAXNEG;
    #pragma unroll
    for (int q = 0; q < 8; q++) {
        gmA = fmaxf(gmA, rmax[q * 64 + rA]);
        gmB = fmaxf(gmB, rmax[q * 64 + rB]);
    }

    float sumA = 0.f, sumB = 0.f;
    #pragma unroll
    for (int nt = 0; nt < 4; nt++) {
        if (nt < ntiles) {
            float eA0 = __expf(sacc[nt][0] - gmA), eA1 = __expf(sacc[nt][1] - gmA);
            float eB0 = __expf(sacc[nt][2] - gmB), eB1 = __expf(sacc[nt][3] - gmB);
            sumA += eA0 + eA1; sumB += eB0 + eB1;
            int c = (n0q >> 1) + nt * 4 + tq;
            psP[rA * SPP + c] = packh2(eA0, eA1);
            psP[rB * SPP + c] = packh2(eB0, eB1);
        }
    }
    sumA += __shfl_xor_sync(0xffffffffu, sumA, 1);
    sumA += __shfl_xor_sync(0xffffffffu, sumA, 2);
    sumB += __shfl_xor_sync(0xffffffffu, sumB, 1);
    sumB += __shfl_xor_sync(0xffffffffu, sumB, 2);
    if (tq == 0) { rsum[nq * 64 + rA] = sumA; rsum[nq * 64 + rB] = sumB; }
    __syncthreads();

    if (w < 16) {
        const int m0o = (w & 3) * 16;
        const int n0o = (w >> 2) * 16;
        const int rA2 = m0o + g, rB2 = rA2 + 8;
        float oacc[2][4];
        #pragma unroll
        for (int nt = 0; nt < 2; nt++)
            #pragma unroll
            for (int e = 0; e < 4; e++) oacc[nt][e] = 0.f;

        #pragma unroll
        for (int k13 = 0; k13 < 13; k13++) {
            const int k2 = k13 * 8;
            uint32_t a0 = psP[rA2 * SPP + k2 + tq];
            uint32_t a1 = psP[rB2 * SPP + k2 + tq];
            uint32_t a2 = psP[rA2 * SPP + k2 + 4 + tq];
            uint32_t a3 = psP[rB2 * SPP + k2 + 4 + tq];
            #pragma unroll
            for (int nt = 0; nt < 2; nt++) {
                int n = n0o + nt * 8 + g;
                uint32_t b0 = vsP[(k2 + tq) * SVP + n];
                uint32_t b1 = vsP[(k2 + 4 + tq) * SVP + n];
                mma16h(oacc[nt], a0, a1, a2, a3, b0, b1);
            }
        }
        float sA = 0.f, sB = 0.f;
        #pragma unroll
        for (int q = 0; q < 8; q++) {
            sA += rsum[q * 64 + rA2];
            sB += rsum[q * 64 + rB2];
        }
        float invA = 1.0f / sA, invB = 1.0f / sB;
        const int gyA = by * 8 + (rA2 >> 3), gxA = bx * 8 + (rA2 & 7);
        const int gyB = by * 8 + (rB2 >> 3), gxB = bx * 8 + (rB2 & 7);
        __half* dstA = &g_AOh[(size_t)(pbase + gyA * 128 + gxA) * INNER + qoff];
        __half* dstB = &g_AOh[(size_t)(pbase + gyB * 128 + gxB) * INNER + qoff];
        #pragma unroll
        for (int nt = 0; nt < 2; nt++) {
            int n = n0o + nt * 8 + tq * 2;
            *(__half2*)&dstA[n] = __floats2half2_rn(oacc[nt][0] * invA, oacc[nt][1] * invA);
            *(__half2*)&dstB[n] = __floats2half2_rn(oacc[nt][2] * invB, oacc[nt][3] * invB);
        }
    }
}

// ---------------------------------------------------------------------------
// Kernel 3: out = AO(fp16) @ Wo + bo. f16 MMA + ldmatrix. (exact R11 version)
// ---------------------------------------------------------------------------
#define SAP 36
__global__ void __launch_bounds__(256) k_out(const float* __restrict__ Wo,
                                             const float* __restrict__ bo,
                                             float* __restrict__ out) {
    extern __shared__ uint32_t smu[];
    uint32_t* AsP = smu;                          // [128][36]
    __half*   Bh  = (__half*)(smu + 128 * SAP);   // [64][136]

    const int t = threadIdx.x, w = t >> 5, lane = t & 31;
    const int qsel = lane >> 3, rsel = lane & 7;
    const int g = lane >> 2, tq = lane & 3;
    const int m0w = (w & 1) * 64, n0w = (w >> 1) * 32;
    const int p0 = blockIdx.x * 128;
    const int b  = p0 >> 14;
    const int y  = (p0 & (HWH - 1)) >> 7;

    float acc[4][4][4];
    #pragma unroll
    for (int mt = 0; mt < 4; mt++)
        #pragma unroll
        for (int nt = 0; nt < 4; nt++)
            #pragma unroll
            for (int e = 0; e < 4; e++) acc[mt][nt][e] = 0.f;

    const uint32_t aB = (uint32_t)__cvta_generic_to_shared(AsP);
    const uint32_t bB = (uint32_t)__cvta_generic_to_shared(Bh);

    for (int kc = 0; kc < 8; kc++) {
        const int K0 = kc * 64;
        __syncthreads();
        for (int idx = t; idx < 128 * 16; idx += 256) {
            int m = idx >> 4, kk = (idx & 15) * 2;
            uint2 v = *(const uint2*)&g_AOh[(size_t)(p0 + m) * INNER + K0 + kk * 2];
            AsP[m * SAP + kk]     = v.x;
            AsP[m * SAP + kk + 1] = v.y;
        }
        for (int idx = t; idx < 64 * 32; idx += 256) {
            int k = idx >> 5, n4 = (idx & 31) * 4;
            float4 v = *(const float4*)&Wo[(size_t)(K0 + k) * CC + n4];
            uint2 hv;
            hv.x = packh2(v.x, v.y);
            hv.y = packh2(v.z, v.w);
            *(uint2*)&Bh[k * SH1 + n4] = hv;
        }
        __syncthreads();

        #pragma unroll
        for (int ks16 = 0; ks16 < 4; ks16++) {
            const int k0 = ks16 * 16;
            const int khA = k0 + (qsel >> 1) * 8;
            uint32_t af[4][4];
            #pragma unroll
            for (int mt = 0; mt < 4; mt++) {
                int m = m0w + mt * 16 + (qsel & 1) * 8 + rsel;
                ldsm4(af[mt], aB + (uint32_t)(m * SAP * 4 + khA * 2));
            }
            const int kkB = k0 + (qsel & 1) * 8 + rsel;
            uint32_t bf[4][2];
            #pragma unroll
            for (int h = 0; h < 2; h++) {
                int n = n0w + h * 16 + (qsel >> 1) * 8;
                uint32_t r4[4];
                ldsm4t(r4, bB + (uint32_t)((kkB * SH1 + n) * 2));
                bf[2 * h][0] = r4[0]; bf[2 * h][1] = r4[1];
                bf[2 * h + 1][0] = r4[2]; bf[2 * h + 1][1] = r4[3];
            }
            #pragma unroll
            for (int nt = 0; nt < 4; nt++)
                #pragma unroll
                for (int mt = 0; mt < 4; mt++)
                    mma16h(acc[mt][nt], af[mt][0], af[mt][1], af[mt][2], af[mt][3],
                           bf[nt][0], bf[nt][1]);
        }
    }

    #pragma unroll
    for (int nt = 0; nt < 4; nt++) {
        int nA = n0w + nt * 8 + tq * 2, nB = nA + 1;
        float biasA = bo[nA], biasB = bo[nB];
        float* colA = out + (size_t)(b * CC + nA) * HWH + y * 128;
        float* colB = out + (size_t)(b * CC + nB) * HWH + y * 128;
        #pragma unroll
        for (int mt = 0; mt < 4; mt++) {
            int m = m0w + mt * 16 + g;
            colA[m]     = acc[mt][nt][0] + biasA;
            colB[m]     = acc[mt][nt][1] + biasB;
            colA[m + 8] = acc[mt][nt][2] + biasA;
            colB[m + 8] = acc[mt][nt][3] + biasB;
        }
    }
}

extern "C" void kernel_launch(void* const* d_in, const int* in_sizes, int n_in,
                              void* d_out, int out_size) {
    const float* x   = (const float*)d_in[0];
    const float* Wq  = (const float*)d_in[1];
    const float* Wkv = (const float*)d_in[2];
    const float* Wo  = (const float*)d_in[3];
    const float* bo  = (const float*)d_in[4];
    float* out = (float*)d_out;

    const int smem1 = 2 * 64 * SH1 * 2;                                  // 34816
    const int smem2 = (64 * SQP + 224 * SKP + 104 * SVP + 64 * SPP
                       + 8 * 64 * 2 + 224) * 4;                          // 106112
    const int smem3 = 128 * SAP * 4 + 64 * SH1 * 2;                      // 35840

    cudaFuncSetAttribute(k_proj, cudaFuncAttributeMaxDynamicSharedMemorySize, smem1);
    cudaFuncSetAttribute(k_attn, cudaFuncAttributeMaxDynamicSharedMemorySize, smem2);
    cudaFuncSetAttribute(k_out,  cudaFuncAttributeMaxDynamicSharedMemorySize, smem3);

    dim3 g1(12, 512);
    k_proj<<<g1, 512, smem1>>>(x, Wq, Wkv);

    dim3 g2(256, 8, 4);
    k_attn<<<g2, 1024, smem2>>>();

    dim3 g3(512);
    k_out<<<g3, 256, smem3>>>(Wo, bo, out);
}